// round 11
// baseline (speedup 1.0000x reference)
#include <cuda_runtime.h>
#include <cuda_bf16.h>
#include <math.h>
#include <stdint.h>

#define E_     8
#define B_     4096
#define D_IN_  1024
#define D_HID_ 2048
#define D_OUT_ 1024
#define G_HID_ 128
#define K_     2

// ==================== f32x2 helpers ====================
__device__ __forceinline__ void unpackf2(unsigned long long v, float& lo, float& hi) {
    asm("mov.b64 {%0, %1}, %2;" : "=f"(lo), "=f"(hi) : "l"(v));
}
#define FMA2(acc, a, b) \
    asm("fma.rn.f32x2 %0, %1, %2, %0;" : "+l"(acc) : "l"(a), "l"(b))

// ==================== device scratch ====================
__device__ int   g_counts[E_];
__device__ int   g_offsets[E_];
__device__ int   g_cursor[E_];
__device__ int   g_tok_e[B_ * K_];
__device__ float g_tok_s[B_ * K_];
__device__ int   g_tok_pos[B_ * K_];
__device__ int   g_pair_token[B_ * K_];
__device__ float g_entropy[B_];

__device__ __align__(16) float g_f1[(size_t)B_ * K_ * D_HID_];
__device__ __align__(16) float g_f2[(size_t)B_ * K_ * D_HID_];
__device__ __align__(16) float g_o_pair[(size_t)B_ * K_ * D_OUT_];

// ==================== small kernels ====================
__global__ void init_kernel() {
    if (threadIdx.x < E_) { g_counts[threadIdx.x] = 0; g_cursor[threadIdx.x] = 0; }
}

__global__ __launch_bounds__(128)
void gate_kernel(const float* __restrict__ x,
                 const float* __restrict__ Wg1, const float* __restrict__ bg1,
                 const float* __restrict__ Wg2, const float* __restrict__ bg2,
                 const float* __restrict__ Wg3, const float* __restrict__ bg3,
                 float* __restrict__ out, long long out_sz)
{
    __shared__ __align__(16) float xs[8][D_IN_];
    __shared__ float s_g1[8][G_HID_];
    __shared__ float s_g2[8][G_HID_];
    __shared__ float s_lg[8][E_];

    const int tid = threadIdx.x;
    const int t0  = blockIdx.x * 8;

    const float4* xg  = reinterpret_cast<const float4*>(x + (size_t)t0 * D_IN_);
    float4*       xsv = reinterpret_cast<float4*>(&xs[0][0]);
    #pragma unroll
    for (int i = 0; i < (8 * D_IN_ / 4) / 128; i++)
        xsv[tid + i * 128] = xg[tid + i * 128];
    __syncthreads();

    float acc[8];
    #pragma unroll
    for (int t = 0; t < 8; t++) acc[t] = 0.f;
    for (int i = 0; i < D_IN_; i++) {
        float w = Wg1[i * G_HID_ + tid];
        #pragma unroll
        for (int t = 0; t < 8; t++) acc[t] = fmaf(xs[t][i], w, acc[t]);
    }
    {
        float b = bg1[tid];
        #pragma unroll
        for (int t = 0; t < 8; t++) s_g1[t][tid] = fmaxf(acc[t] + b, 0.f);
    }
    __syncthreads();

    #pragma unroll
    for (int t = 0; t < 8; t++) acc[t] = 0.f;
    for (int i = 0; i < G_HID_; i++) {
        float w = Wg2[i * G_HID_ + tid];
        #pragma unroll
        for (int t = 0; t < 8; t++) acc[t] = fmaf(s_g1[t][i], w, acc[t]);
    }
    {
        float b = bg2[tid];
        #pragma unroll
        for (int t = 0; t < 8; t++) s_g2[t][tid] = fmaxf(acc[t] + b, 0.f);
    }
    __syncthreads();

    if (tid < 64) {
        int t = tid >> 3, e = tid & 7;
        float a = bg3[e];
        for (int i = 0; i < G_HID_; i++)
            a = fmaf(s_g2[t][i], Wg3[i * E_ + e], a);
        s_lg[t][e] = a;
    }
    __syncthreads();

    if (tid < 8) {
        const int t   = tid;
        const int tok = t0 + t;
        float p[E_];
        float mx = s_lg[t][0];
        #pragma unroll
        for (int e = 1; e < E_; e++) mx = fmaxf(mx, s_lg[t][e]);
        float s = 0.f;
        #pragma unroll
        for (int e = 0; e < E_; e++) { p[e] = expf(s_lg[t][e] - mx); s += p[e]; }
        float inv = 1.f / s;
        float ent = 0.f;
        #pragma unroll
        for (int e = 0; e < E_; e++) { p[e] *= inv; ent -= p[e] * logf(p[e] + 1e-9f); }
        g_entropy[tok] = ent;

        int i1 = 0;
        #pragma unroll
        for (int e = 1; e < E_; e++) if (p[e] > p[i1]) i1 = e;
        int i2 = (i1 == 0) ? 1 : 0;
        #pragma unroll
        for (int e = 0; e < E_; e++) if (e != i1 && p[e] > p[i2]) i2 = e;

        float s1 = p[i1], s2 = p[i2];
        atomicAdd(&g_counts[i1], 1);
        atomicAdd(&g_counts[i2], 1);
        float denom = s1 + s2 + 1e-9f;
        g_tok_e[tok * 2 + 0] = i1;
        g_tok_e[tok * 2 + 1] = i2;
        g_tok_s[tok * 2 + 0] = s1 / denom;
        g_tok_s[tok * 2 + 1] = s2 / denom;

        long long idx_off = (long long)B_ * D_OUT_ + 1;
        long long sc_off  = idx_off + (long long)B_ * K_;
        if (out_sz >= sc_off + (long long)B_ * K_) {
            out[idx_off + tok * 2 + 0] = (float)i1;
            out[idx_off + tok * 2 + 1] = (float)i2;
            out[sc_off  + tok * 2 + 0] = s1;
            out[sc_off  + tok * 2 + 1] = s2;
        }
    }
}

__global__ void offsets_kernel() {
    if (threadIdx.x == 0 && blockIdx.x == 0) {
        int off = 0;
        for (int e = 0; e < E_; e++) {
            g_offsets[e] = off;
            g_cursor[e]  = off;
            off += g_counts[e];
        }
    }
}

__global__ void scatter_kernel() {
    int tok = blockIdx.x * blockDim.x + threadIdx.x;
    if (tok >= B_) return;
    #pragma unroll
    for (int k = 0; k < K_; k++) {
        int e = g_tok_e[tok * 2 + k];
        int pos = atomicAdd(&g_cursor[e], 1);
        g_pair_token[pos] = tok;
        g_tok_pos[tok * 2 + k] = pos;
    }
}

// ==================== f32x2 packed GEMM, pre-packed smem ====================
#define BM 128
#define BN 128
#define BK 8

// thread (tx=tid&15, ty=tid>>4): rows ty*8+[0,8), cols n0 + tx + 32p (+16), p=0..3.
// As2[k][m]      = (A[m][k], A[m][k])           -- duplicated pair
// Bs2[k][p*16+r] = (B[k][n0+32p+r], B[k][n0+32p+16+r])
template<int KDIM, int NDIM, int EPI, int ASRC>
__global__ __launch_bounds__(256, 2)
void moe_gemm2(const float* __restrict__ xptr,
               const float* __restrict__ Wstack,
               const float* __restrict__ bstack)
{
    const int e   = blockIdx.z;
    const int cnt = g_counts[e];
    const int m0  = blockIdx.y * BM;
    if (m0 >= cnt) return;
    const int off = g_offsets[e];
    const int n0  = blockIdx.x * BN;

    const float* __restrict__ Wb = Wstack + (size_t)e * KDIM * NDIM;
    const float* __restrict__ Abase =
        (ASRC == 0) ? xptr : (ASRC == 1 ? (const float*)g_f1 : (const float*)g_f2);
    float* __restrict__ Obase =
        (EPI == 0) ? (ASRC == 0 ? (float*)g_f1 : (float*)g_f2) : (float*)g_o_pair;

    __shared__ __align__(16) float2 As2[2][BK][BM];       // 16 KB
    __shared__ __align__(16) float2 Bs2[2][BK][BN / 2];   //  8 KB

    const int tid   = threadIdx.x;
    const int a_row = tid >> 1;
    const int a_kq  = (tid & 1) << 2;
    const int b_k   = tid >> 5;
    const int b_n   = (tid & 31) << 2;
    // B pair-slot for this thread's 4 columns (all in the same 32-group & half)
    const int b_p    = b_n >> 5;
    const int b_r    = b_n & 31;
    const int b_half = (b_r >> 4);            // 0 => lo element, 1 => hi element
    const int b_j    = b_p * 16 + (b_r & 15); // pair index of first column

    int m  = m0 + a_row;
    int mm = (m < cnt) ? m : (cnt - 1);
    const float* __restrict__ Arow =
        (ASRC == 0) ? Abase + (size_t)g_pair_token[off + mm] * KDIM
                    : Abase + (size_t)(off + mm) * KDIM;

    const int tx = tid & 15;
    const int ty = tid >> 4;

    unsigned long long acc2[8][4];
    #pragma unroll
    for (int i = 0; i < 8; i++)
        #pragma unroll
        for (int p = 0; p < 4; p++) acc2[i][p] = 0ULL;

    auto store_tile = [&](int buf, const float4& av, const float4& bv) {
        As2[buf][a_kq + 0][a_row] = make_float2(av.x, av.x);
        As2[buf][a_kq + 1][a_row] = make_float2(av.y, av.y);
        As2[buf][a_kq + 2][a_row] = make_float2(av.z, av.z);
        As2[buf][a_kq + 3][a_row] = make_float2(av.w, av.w);
        float* c0 = reinterpret_cast<float*>(&Bs2[buf][b_k][b_j]) + b_half;
        c0[0] = bv.x;  c0[2] = bv.y;  c0[4] = bv.z;  c0[6] = bv.w;
    };

    // prologue: tile 0
    {
        float4 av = *reinterpret_cast<const float4*>(Arow + a_kq);
        float4 bv = *reinterpret_cast<const float4*>(Wb + (size_t)b_k * NDIM + n0 + b_n);
        store_tile(0, av, bv);
    }
    __syncthreads();

    const int ntiles = KDIM / BK;
    for (int t = 0; t < ntiles; ++t) {
        const int cur = t & 1;
        const int nxt = cur ^ 1;
        float4 an, bn;
        if (t + 1 < ntiles) {
            const int k0 = (t + 1) * BK;
            an = *reinterpret_cast<const float4*>(Arow + k0 + a_kq);
            bn = *reinterpret_cast<const float4*>(Wb + (size_t)(k0 + b_k) * NDIM + n0 + b_n);
        }
        #pragma unroll
        for (int kk = 0; kk < BK; kk++) {
            unsigned long long ar2[8];
            {
                const ulonglong2* ap =
                    reinterpret_cast<const ulonglong2*>(&As2[cur][kk][ty * 8]);
                ulonglong2 u0 = ap[0], u1 = ap[1], u2 = ap[2], u3 = ap[3];
                ar2[0] = u0.x; ar2[1] = u0.y;
                ar2[2] = u1.x; ar2[3] = u1.y;
                ar2[4] = u2.x; ar2[5] = u2.y;
                ar2[6] = u3.x; ar2[7] = u3.y;
            }
            unsigned long long brp[4];
            #pragma unroll
            for (int p = 0; p < 4; p++)
                brp[p] = *reinterpret_cast<const unsigned long long*>(&Bs2[cur][kk][p * 16 + tx]);
            #pragma unroll
            for (int i = 0; i < 8; i++)
                #pragma unroll
                for (int p = 0; p < 4; p++)
                    FMA2(acc2[i][p], ar2[i], brp[p]);
        }
        if (t + 1 < ntiles) store_tile(nxt, an, bn);
        __syncthreads();
    }

    // epilogue: cols n0 + tx + 32p (+16)
    float bias0[4], bias1[4];
    #pragma unroll
    for (int p = 0; p < 4; p++) {
        bias0[p] = bstack[(size_t)e * NDIM + n0 + tx + 32 * p];
        bias1[p] = bstack[(size_t)e * NDIM + n0 + tx + 32 * p + 16];
    }
    #pragma unroll
    for (int i = 0; i < 8; i++) {
        int mr = m0 + ty * 8 + i;
        if (mr >= cnt) continue;
        float* orow = Obase + (size_t)(off + mr) * NDIM + n0 + tx;
        #pragma unroll
        for (int p = 0; p < 4; p++) {
            float lo, hi;
            unpackf2(acc2[i][p], lo, hi);
            float v0 = lo + bias0[p];
            float v1 = hi + bias1[p];
            if (EPI == 0) { v0 = fmaxf(v0, 0.f); v1 = fmaxf(v1, 0.f); }
            orow[32 * p]      = v0;
            orow[32 * p + 16] = v1;
        }
    }
}

// ==================== combine + finalize ====================
__global__ __launch_bounds__(256)
void combine_kernel(float* __restrict__ out)
{
    int i = blockIdx.x * 256 + threadIdx.x;
    int tok = i >> 10, c = i & 1023;
    float v = g_tok_s[tok * 2 + 0] * g_o_pair[(size_t)g_tok_pos[tok * 2 + 0] * D_OUT_ + c]
            + g_tok_s[tok * 2 + 1] * g_o_pair[(size_t)g_tok_pos[tok * 2 + 1] * D_OUT_ + c];
    out[i] = v;
}

__global__ __launch_bounds__(1024)
void finalize_kernel(float* __restrict__ out, long long out_sz)
{
    __shared__ float red[1024];
    const int tid = threadIdx.x;
    float s = 0.f;
    for (int i = tid; i < B_; i += 1024) s += g_entropy[i];
    red[tid] = s;
    __syncthreads();
    for (int st = 512; st > 0; st >>= 1) {
        if (tid < st) red[tid] += red[tid + st];
        __syncthreads();
    }
    if (tid == 0) {
        float ent_mean = red[0] / (float)B_;
        float load[E_];
        float mean = 0.f;
        for (int e = 0; e < E_; e++) {
            load[e] = (float)g_counts[e] / ((float)B_ + 1e-9f);
            mean += load[e];
        }
        mean /= (float)E_;
        float var = 0.f;
        for (int e = 0; e < E_; e++) {
            float d = load[e] - mean;
            var += d * d;
        }
        var /= (float)(E_ - 1);
        float aux = 5.0f * var + 0.1f * ent_mean;
        long long aux_off = (long long)B_ * D_OUT_;
        if (out_sz > aux_off) out[aux_off] = aux;
    }
}

// ==================== launch ====================
extern "C" void kernel_launch(void* const* d_in, const int* in_sizes, int n_in,
                              void* d_out, int out_size)
{
    const float* x   = (const float*)d_in[0];
    const float* We1 = (const float*)d_in[1];
    const float* be1 = (const float*)d_in[2];
    const float* We2 = (const float*)d_in[3];
    const float* be2 = (const float*)d_in[4];
    const float* We3 = (const float*)d_in[5];
    const float* be3 = (const float*)d_in[6];
    const float* Wg1 = (const float*)d_in[7];
    const float* bg1 = (const float*)d_in[8];
    const float* Wg2 = (const float*)d_in[9];
    const float* bg2 = (const float*)d_in[10];
    const float* Wg3 = (const float*)d_in[11];
    const float* bg3 = (const float*)d_in[12];
    float* out = (float*)d_out;
    long long out_sz = (long long)out_size;

    init_kernel<<<1, 32>>>();
    gate_kernel<<<B_ / 8, 128>>>(x, Wg1, bg1, Wg2, bg2, Wg3, bg3, out, out_sz);
    offsets_kernel<<<1, 32>>>();
    scatter_kernel<<<(B_ + 255) / 256, 256>>>();

    const int max_mt = B_ / 128;   // per-expert cnt <= B
    dim3 g1(D_HID_ / BN, max_mt, E_);
    dim3 g3(D_OUT_ / BN, max_mt, E_);

    moe_gemm2<D_IN_,  D_HID_, 0, 0><<<g1, 256>>>(x, We1, be1);
    moe_gemm2<D_HID_, D_HID_, 0, 1><<<g1, 256>>>(x, We2, be2);
    moe_gemm2<D_HID_, D_OUT_, 2, 2><<<g3, 256>>>(x, We3, be3);

    combine_kernel<<<(B_ * D_OUT_) / 256, 256>>>(out);
    finalize_kernel<<<1, 1024>>>(out, out_sz);
}

// round 12
// speedup vs baseline: 1.0000x; 1.0000x over previous
#include <cuda_runtime.h>
#include <cuda_bf16.h>
#include <math.h>
#include <stdint.h>

#define E_     8
#define B_     4096
#define D_IN_  1024
#define D_HID_ 2048
#define D_OUT_ 1024
#define G_HID_ 128
#define K_     2

// ==================== f32x2 helpers ====================
__device__ __forceinline__ void unpackf2(unsigned long long v, float& lo, float& hi) {
    asm("mov.b64 {%0, %1}, %2;" : "=f"(lo), "=f"(hi) : "l"(v));
}
#define FMA2(acc, a, b) \
    asm("fma.rn.f32x2 %0, %1, %2, %0;" : "+l"(acc) : "l"(a), "l"(b))

// ==================== device scratch ====================
__device__ int   g_counts[E_];
__device__ int   g_offsets[E_];
__device__ int   g_cursor[E_];
__device__ int   g_tok_e[B_ * K_];
__device__ float g_tok_s[B_ * K_];
__device__ int   g_tok_pos[B_ * K_];
__device__ int   g_pair_token[B_ * K_];
__device__ float g_entropy[B_];

__device__ __align__(16) float g_f1[(size_t)B_ * K_ * D_HID_];
__device__ __align__(16) float g_f2[(size_t)B_ * K_ * D_HID_];
__device__ __align__(16) float g_o_pair[(size_t)B_ * K_ * D_OUT_];

// ==================== small kernels ====================
__global__ void init_kernel() {
    if (threadIdx.x < E_) { g_counts[threadIdx.x] = 0; g_cursor[threadIdx.x] = 0; }
}

__global__ __launch_bounds__(128)
void gate_kernel(const float* __restrict__ x,
                 const float* __restrict__ Wg1, const float* __restrict__ bg1,
                 const float* __restrict__ Wg2, const float* __restrict__ bg2,
                 const float* __restrict__ Wg3, const float* __restrict__ bg3,
                 float* __restrict__ out, long long out_sz)
{
    __shared__ __align__(16) float xs[8][D_IN_];
    __shared__ float s_g1[8][G_HID_];
    __shared__ float s_g2[8][G_HID_];
    __shared__ float s_lg[8][E_];

    const int tid = threadIdx.x;
    const int t0  = blockIdx.x * 8;

    const float4* xg  = reinterpret_cast<const float4*>(x + (size_t)t0 * D_IN_);
    float4*       xsv = reinterpret_cast<float4*>(&xs[0][0]);
    #pragma unroll
    for (int i = 0; i < (8 * D_IN_ / 4) / 128; i++)
        xsv[tid + i * 128] = xg[tid + i * 128];
    __syncthreads();

    float acc[8];
    #pragma unroll
    for (int t = 0; t < 8; t++) acc[t] = 0.f;
    for (int i = 0; i < D_IN_; i++) {
        float w = Wg1[i * G_HID_ + tid];
        #pragma unroll
        for (int t = 0; t < 8; t++) acc[t] = fmaf(xs[t][i], w, acc[t]);
    }
    {
        float b = bg1[tid];
        #pragma unroll
        for (int t = 0; t < 8; t++) s_g1[t][tid] = fmaxf(acc[t] + b, 0.f);
    }
    __syncthreads();

    #pragma unroll
    for (int t = 0; t < 8; t++) acc[t] = 0.f;
    for (int i = 0; i < G_HID_; i++) {
        float w = Wg2[i * G_HID_ + tid];
        #pragma unroll
        for (int t = 0; t < 8; t++) acc[t] = fmaf(s_g1[t][i], w, acc[t]);
    }
    {
        float b = bg2[tid];
        #pragma unroll
        for (int t = 0; t < 8; t++) s_g2[t][tid] = fmaxf(acc[t] + b, 0.f);
    }
    __syncthreads();

    if (tid < 64) {
        int t = tid >> 3, e = tid & 7;
        float a = bg3[e];
        for (int i = 0; i < G_HID_; i++)
            a = fmaf(s_g2[t][i], Wg3[i * E_ + e], a);
        s_lg[t][e] = a;
    }
    __syncthreads();

    if (tid < 8) {
        const int t   = tid;
        const int tok = t0 + t;
        float p[E_];
        float mx = s_lg[t][0];
        #pragma unroll
        for (int e = 1; e < E_; e++) mx = fmaxf(mx, s_lg[t][e]);
        float s = 0.f;
        #pragma unroll
        for (int e = 0; e < E_; e++) { p[e] = expf(s_lg[t][e] - mx); s += p[e]; }
        float inv = 1.f / s;
        float ent = 0.f;
        #pragma unroll
        for (int e = 0; e < E_; e++) { p[e] *= inv; ent -= p[e] * logf(p[e] + 1e-9f); }
        g_entropy[tok] = ent;

        int i1 = 0;
        #pragma unroll
        for (int e = 1; e < E_; e++) if (p[e] > p[i1]) i1 = e;
        int i2 = (i1 == 0) ? 1 : 0;
        #pragma unroll
        for (int e = 0; e < E_; e++) if (e != i1 && p[e] > p[i2]) i2 = e;

        float s1 = p[i1], s2 = p[i2];
        atomicAdd(&g_counts[i1], 1);
        atomicAdd(&g_counts[i2], 1);
        float denom = s1 + s2 + 1e-9f;
        g_tok_e[tok * 2 + 0] = i1;
        g_tok_e[tok * 2 + 1] = i2;
        g_tok_s[tok * 2 + 0] = s1 / denom;
        g_tok_s[tok * 2 + 1] = s2 / denom;

        long long idx_off = (long long)B_ * D_OUT_ + 1;
        long long sc_off  = idx_off + (long long)B_ * K_;
        if (out_sz >= sc_off + (long long)B_ * K_) {
            out[idx_off + tok * 2 + 0] = (float)i1;
            out[idx_off + tok * 2 + 1] = (float)i2;
            out[sc_off  + tok * 2 + 0] = s1;
            out[sc_off  + tok * 2 + 1] = s2;
        }
    }
}

__global__ void offsets_kernel() {
    if (threadIdx.x == 0 && blockIdx.x == 0) {
        int off = 0;
        for (int e = 0; e < E_; e++) {
            g_offsets[e] = off;
            g_cursor[e]  = off;
            off += g_counts[e];
        }
    }
}

__global__ void scatter_kernel() {
    int tok = blockIdx.x * blockDim.x + threadIdx.x;
    if (tok >= B_) return;
    #pragma unroll
    for (int k = 0; k < K_; k++) {
        int e = g_tok_e[tok * 2 + k];
        int pos = atomicAdd(&g_cursor[e], 1);
        g_pair_token[pos] = tok;
        g_tok_pos[tok * 2 + k] = pos;
    }
}

// ==================== f32x2 packed GEMM, pre-packed smem, uncapped regs =======
#define BM 128
#define BN 128
#define BK 8

// thread (tx=tid&15, ty=tid>>4): rows ty*8+[0,8), cols n0 + tx + 32p (+16), p=0..3.
// As2[k][m]      = (A[m][k], A[m][k])           -- duplicated pair
// Bs2[k][p*16+r] = (B[k][n0+32p+r], B[k][n0+32p+16+r])
template<int KDIM, int NDIM, int EPI, int ASRC>
__global__ __launch_bounds__(256)
void moe_gemm2(const float* __restrict__ xptr,
               const float* __restrict__ Wstack,
               const float* __restrict__ bstack)
{
    const int e   = blockIdx.z;
    const int cnt = g_counts[e];
    const int m0  = blockIdx.y * BM;
    if (m0 >= cnt) return;
    const int off = g_offsets[e];
    const int n0  = blockIdx.x * BN;

    const float* __restrict__ Wb = Wstack + (size_t)e * KDIM * NDIM;
    const float* __restrict__ Abase =
        (ASRC == 0) ? xptr : (ASRC == 1 ? (const float*)g_f1 : (const float*)g_f2);
    float* __restrict__ Obase =
        (EPI == 0) ? (ASRC == 0 ? (float*)g_f1 : (float*)g_f2) : (float*)g_o_pair;

    __shared__ __align__(16) float2 As2[2][BK][BM];       // 16 KB
    __shared__ __align__(16) float2 Bs2[2][BK][BN / 2];   //  8 KB

    const int tid   = threadIdx.x;
    const int a_row = tid >> 1;
    const int a_kq  = (tid & 1) << 2;
    const int b_k   = tid >> 5;
    const int b_n   = (tid & 31) << 2;
    // B pair-slot for this thread's 4 columns (all in the same 32-group & half)
    const int b_p    = b_n >> 5;
    const int b_r    = b_n & 31;
    const int b_half = (b_r >> 4);            // 0 => lo element, 1 => hi element
    const int b_j    = b_p * 16 + (b_r & 15); // pair index of first column

    int m  = m0 + a_row;
    int mm = (m < cnt) ? m : (cnt - 1);
    const float* __restrict__ Arow =
        (ASRC == 0) ? Abase + (size_t)g_pair_token[off + mm] * KDIM
                    : Abase + (size_t)(off + mm) * KDIM;

    const int tx = tid & 15;
    const int ty = tid >> 4;

    unsigned long long acc2[8][4];
    #pragma unroll
    for (int i = 0; i < 8; i++)
        #pragma unroll
        for (int p = 0; p < 4; p++) acc2[i][p] = 0ULL;

    auto store_tile = [&](int buf, const float4& av, const float4& bv) {
        As2[buf][a_kq + 0][a_row] = make_float2(av.x, av.x);
        As2[buf][a_kq + 1][a_row] = make_float2(av.y, av.y);
        As2[buf][a_kq + 2][a_row] = make_float2(av.z, av.z);
        As2[buf][a_kq + 3][a_row] = make_float2(av.w, av.w);
        float* c0 = reinterpret_cast<float*>(&Bs2[buf][b_k][b_j]) + b_half;
        c0[0] = bv.x;  c0[2] = bv.y;  c0[4] = bv.z;  c0[6] = bv.w;
    };

    // prologue: tile 0
    {
        float4 av = *reinterpret_cast<const float4*>(Arow + a_kq);
        float4 bv = *reinterpret_cast<const float4*>(Wb + (size_t)b_k * NDIM + n0 + b_n);
        store_tile(0, av, bv);
    }
    __syncthreads();

    const int ntiles = KDIM / BK;
    for (int t = 0; t < ntiles; ++t) {
        const int cur = t & 1;
        const int nxt = cur ^ 1;
        float4 an, bn;
        if (t + 1 < ntiles) {
            const int k0 = (t + 1) * BK;
            an = *reinterpret_cast<const float4*>(Arow + k0 + a_kq);
            bn = *reinterpret_cast<const float4*>(Wb + (size_t)(k0 + b_k) * NDIM + n0 + b_n);
        }
        #pragma unroll
        for (int kk = 0; kk < BK; kk++) {
            unsigned long long ar2[8];
            #pragma unroll
            for (int q = 0; q < 4; q++) {
                ulonglong2 u = reinterpret_cast<const ulonglong2*>(&As2[cur][kk][ty * 8])[q];
                ar2[q * 2]     = u.x;
                ar2[q * 2 + 1] = u.y;
            }
            unsigned long long brp[4];
            #pragma unroll
            for (int p = 0; p < 4; p++)
                brp[p] = *reinterpret_cast<const unsigned long long*>(&Bs2[cur][kk][p * 16 + tx]);
            #pragma unroll
            for (int i = 0; i < 8; i++)
                #pragma unroll
                for (int p = 0; p < 4; p++)
                    FMA2(acc2[i][p], ar2[i], brp[p]);
        }
        if (t + 1 < ntiles) store_tile(nxt, an, bn);
        __syncthreads();
    }

    // epilogue: cols n0 + tx + 32p (+16)
    float bias0[4], bias1[4];
    #pragma unroll
    for (int p = 0; p < 4; p++) {
        bias0[p] = bstack[(size_t)e * NDIM + n0 + tx + 32 * p];
        bias1[p] = bstack[(size_t)e * NDIM + n0 + tx + 32 * p + 16];
    }
    #pragma unroll
    for (int i = 0; i < 8; i++) {
        int mr = m0 + ty * 8 + i;
        if (mr >= cnt) continue;
        float* orow = Obase + (size_t)(off + mr) * NDIM + n0 + tx;
        #pragma unroll
        for (int p = 0; p < 4; p++) {
            float lo, hi;
            unpackf2(acc2[i][p], lo, hi);
            float v0 = lo + bias0[p];
            float v1 = hi + bias1[p];
            if (EPI == 0) { v0 = fmaxf(v0, 0.f); v1 = fmaxf(v1, 0.f); }
            orow[32 * p]      = v0;
            orow[32 * p + 16] = v1;
        }
    }
}

// ==================== combine + finalize ====================
__global__ __launch_bounds__(256)
void combine_kernel(float* __restrict__ out)
{
    int i = blockIdx.x * 256 + threadIdx.x;
    int tok = i >> 10, c = i & 1023;
    float v = g_tok_s[tok * 2 + 0] * g_o_pair[(size_t)g_tok_pos[tok * 2 + 0] * D_OUT_ + c]
            + g_tok_s[tok * 2 + 1] * g_o_pair[(size_t)g_tok_pos[tok * 2 + 1] * D_OUT_ + c];
    out[i] = v;
}

__global__ __launch_bounds__(1024)
void finalize_kernel(float* __restrict__ out, long long out_sz)
{
    __shared__ float red[1024];
    const int tid = threadIdx.x;
    float s = 0.f;
    for (int i = tid; i < B_; i += 1024) s += g_entropy[i];
    red[tid] = s;
    __syncthreads();
    for (int st = 512; st > 0; st >>= 1) {
        if (tid < st) red[tid] += red[tid + st];
        __syncthreads();
    }
    if (tid == 0) {
        float ent_mean = red[0] / (float)B_;
        float load[E_];
        float mean = 0.f;
        for (int e = 0; e < E_; e++) {
            load[e] = (float)g_counts[e] / ((float)B_ + 1e-9f);
            mean += load[e];
        }
        mean /= (float)E_;
        float var = 0.f;
        for (int e = 0; e < E_; e++) {
            float d = load[e] - mean;
            var += d * d;
        }
        var /= (float)(E_ - 1);
        float aux = 5.0f * var + 0.1f * ent_mean;
        long long aux_off = (long long)B_ * D_OUT_;
        if (out_sz > aux_off) out[aux_off] = aux;
    }
}

// ==================== launch ====================
extern "C" void kernel_launch(void* const* d_in, const int* in_sizes, int n_in,
                              void* d_out, int out_size)
{
    const float* x   = (const float*)d_in[0];
    const float* We1 = (const float*)d_in[1];
    const float* be1 = (const float*)d_in[2];
    const float* We2 = (const float*)d_in[3];
    const float* be2 = (const float*)d_in[4];
    const float* We3 = (const float*)d_in[5];
    const float* be3 = (const float*)d_in[6];
    const float* Wg1 = (const float*)d_in[7];
    const float* bg1 = (const float*)d_in[8];
    const float* Wg2 = (const float*)d_in[9];
    const float* bg2 = (const float*)d_in[10];
    const float* Wg3 = (const float*)d_in[11];
    const float* bg3 = (const float*)d_in[12];
    float* out = (float*)d_out;
    long long out_sz = (long long)out_size;

    init_kernel<<<1, 32>>>();
    gate_kernel<<<B_ / 8, 128>>>(x, Wg1, bg1, Wg2, bg2, Wg3, bg3, out, out_sz);
    offsets_kernel<<<1, 32>>>();
    scatter_kernel<<<(B_ + 255) / 256, 256>>>();

    const int max_mt = B_ / 128;   // per-expert cnt <= B
    dim3 g1(D_HID_ / BN, max_mt, E_);
    dim3 g3(D_OUT_ / BN, max_mt, E_);

    moe_gemm2<D_IN_,  D_HID_, 0, 0><<<g1, 256>>>(x, We1, be1);
    moe_gemm2<D_HID_, D_HID_, 0, 1><<<g1, 256>>>(x, We2, be2);
    moe_gemm2<D_HID_, D_OUT_, 2, 2><<<g3, 256>>>(x, We3, be3);

    combine_kernel<<<(B_ * D_OUT_) / 256, 256>>>(out);
    finalize_kernel<<<1, 1024>>>(out, out_sz);
}

// round 13
// speedup vs baseline: 1.2016x; 1.2016x over previous
#include <cuda_runtime.h>
#include <cuda_bf16.h>
#include <math.h>
#include <stdint.h>

#define E_     8
#define B_     4096
#define D_IN_  1024
#define D_HID_ 2048
#define D_OUT_ 1024
#define G_HID_ 128
#define K_     2

// ==================== f32x2 helpers ====================
__device__ __forceinline__ unsigned long long packf2(float lo, float hi) {
    unsigned long long r;
    asm("mov.b64 %0, {%1, %2};" : "=l"(r) : "f"(lo), "f"(hi));
    return r;
}
__device__ __forceinline__ void unpackf2(unsigned long long v, float& lo, float& hi) {
    asm("mov.b64 {%0, %1}, %2;" : "=f"(lo), "=f"(hi) : "l"(v));
}
#define FMA2(acc, a, b) \
    asm("fma.rn.f32x2 %0, %1, %2, %0;" : "+l"(acc) : "l"(a), "l"(b))

// ==================== device scratch ====================
__device__ int   g_counts[E_];
__device__ int   g_offsets[E_];
__device__ int   g_cursor[E_];
__device__ int   g_tok_e[B_ * K_];
__device__ float g_tok_s[B_ * K_];
__device__ int   g_tok_pos[B_ * K_];
__device__ int   g_pair_token[B_ * K_];
__device__ float g_entropy[B_];

__device__ __align__(16) float g_f1[(size_t)B_ * K_ * D_HID_];
__device__ __align__(16) float g_f2[(size_t)B_ * K_ * D_HID_];
__device__ __align__(16) float g_o_pair[(size_t)B_ * K_ * D_OUT_];

// ==================== small kernels ====================
__global__ void init_kernel() {
    if (threadIdx.x < E_) { g_counts[threadIdx.x] = 0; g_cursor[threadIdx.x] = 0; }
}

__global__ __launch_bounds__(128)
void gate_kernel(const float* __restrict__ x,
                 const float* __restrict__ Wg1, const float* __restrict__ bg1,
                 const float* __restrict__ Wg2, const float* __restrict__ bg2,
                 const float* __restrict__ Wg3, const float* __restrict__ bg3,
                 float* __restrict__ out, long long out_sz)
{
    __shared__ __align__(16) float xs[8][D_IN_];
    __shared__ float s_g1[8][G_HID_];
    __shared__ float s_g2[8][G_HID_];
    __shared__ float s_lg[8][E_];

    const int tid = threadIdx.x;
    const int t0  = blockIdx.x * 8;

    const float4* xg  = reinterpret_cast<const float4*>(x + (size_t)t0 * D_IN_);
    float4*       xsv = reinterpret_cast<float4*>(&xs[0][0]);
    #pragma unroll
    for (int i = 0; i < (8 * D_IN_ / 4) / 128; i++)
        xsv[tid + i * 128] = xg[tid + i * 128];
    __syncthreads();

    float acc[8];
    #pragma unroll
    for (int t = 0; t < 8; t++) acc[t] = 0.f;
    for (int i = 0; i < D_IN_; i++) {
        float w = Wg1[i * G_HID_ + tid];
        #pragma unroll
        for (int t = 0; t < 8; t++) acc[t] = fmaf(xs[t][i], w, acc[t]);
    }
    {
        float b = bg1[tid];
        #pragma unroll
        for (int t = 0; t < 8; t++) s_g1[t][tid] = fmaxf(acc[t] + b, 0.f);
    }
    __syncthreads();

    #pragma unroll
    for (int t = 0; t < 8; t++) acc[t] = 0.f;
    for (int i = 0; i < G_HID_; i++) {
        float w = Wg2[i * G_HID_ + tid];
        #pragma unroll
        for (int t = 0; t < 8; t++) acc[t] = fmaf(s_g1[t][i], w, acc[t]);
    }
    {
        float b = bg2[tid];
        #pragma unroll
        for (int t = 0; t < 8; t++) s_g2[t][tid] = fmaxf(acc[t] + b, 0.f);
    }
    __syncthreads();

    if (tid < 64) {
        int t = tid >> 3, e = tid & 7;
        float a = bg3[e];
        for (int i = 0; i < G_HID_; i++)
            a = fmaf(s_g2[t][i], Wg3[i * E_ + e], a);
        s_lg[t][e] = a;
    }
    __syncthreads();

    if (tid < 8) {
        const int t   = tid;
        const int tok = t0 + t;
        float p[E_];
        float mx = s_lg[t][0];
        #pragma unroll
        for (int e = 1; e < E_; e++) mx = fmaxf(mx, s_lg[t][e]);
        float s = 0.f;
        #pragma unroll
        for (int e = 0; e < E_; e++) { p[e] = expf(s_lg[t][e] - mx); s += p[e]; }
        float inv = 1.f / s;
        float ent = 0.f;
        #pragma unroll
        for (int e = 0; e < E_; e++) { p[e] *= inv; ent -= p[e] * logf(p[e] + 1e-9f); }
        g_entropy[tok] = ent;

        int i1 = 0;
        #pragma unroll
        for (int e = 1; e < E_; e++) if (p[e] > p[i1]) i1 = e;
        int i2 = (i1 == 0) ? 1 : 0;
        #pragma unroll
        for (int e = 0; e < E_; e++) if (e != i1 && p[e] > p[i2]) i2 = e;

        float s1 = p[i1], s2 = p[i2];
        atomicAdd(&g_counts[i1], 1);
        atomicAdd(&g_counts[i2], 1);
        float denom = s1 + s2 + 1e-9f;
        g_tok_e[tok * 2 + 0] = i1;
        g_tok_e[tok * 2 + 1] = i2;
        g_tok_s[tok * 2 + 0] = s1 / denom;
        g_tok_s[tok * 2 + 1] = s2 / denom;

        long long idx_off = (long long)B_ * D_OUT_ + 1;
        long long sc_off  = idx_off + (long long)B_ * K_;
        if (out_sz >= sc_off + (long long)B_ * K_) {
            out[idx_off + tok * 2 + 0] = (float)i1;
            out[idx_off + tok * 2 + 1] = (float)i2;
            out[sc_off  + tok * 2 + 0] = s1;
            out[sc_off  + tok * 2 + 1] = s2;
        }
    }
}

__global__ void offsets_kernel() {
    if (threadIdx.x == 0 && blockIdx.x == 0) {
        int off = 0;
        for (int e = 0; e < E_; e++) {
            g_offsets[e] = off;
            g_cursor[e]  = off;
            off += g_counts[e];
        }
    }
}

__global__ void scatter_kernel() {
    int tok = blockIdx.x * blockDim.x + threadIdx.x;
    if (tok >= B_) return;
    #pragma unroll
    for (int k = 0; k < K_; k++) {
        int e = g_tok_e[tok * 2 + k];
        int pos = atomicAdd(&g_cursor[e], 1);
        g_pair_token[pos] = tok;
        g_tok_pos[tok * 2 + k] = pos;
    }
}

// ==================== f32x2 packed GEMM (round-10 proven engine) ====================
#define BM 128
#define BN 128
#define BK 8

// 256 threads; thread (tx=tid&15, ty=tid>>4): rows ty*8+[0,8), cols n0 + tx + 32p (+16), p=0..3.
template<int KDIM, int NDIM, int EPI, int ASRC>
__global__ __launch_bounds__(256)
void moe_gemm2(const float* __restrict__ xptr,
               const float* __restrict__ Wstack,
               const float* __restrict__ bstack)
{
    const int e   = blockIdx.z;
    const int cnt = g_counts[e];
    const int m0  = blockIdx.y * BM;
    if (m0 >= cnt) return;
    const int off = g_offsets[e];
    const int n0  = blockIdx.x * BN;

    const float* __restrict__ Wb = Wstack + (size_t)e * KDIM * NDIM;
    const float* __restrict__ Abase =
        (ASRC == 0) ? xptr : (ASRC == 1 ? (const float*)g_f1 : (const float*)g_f2);
    float* __restrict__ Obase =
        (EPI == 0) ? (ASRC == 0 ? (float*)g_f1 : (float*)g_f2) : (float*)g_o_pair;

    __shared__ __align__(16) float As[2][BK][BM];
    __shared__ __align__(16) float Bs[2][BK][BN];

    const int tid   = threadIdx.x;
    const int a_row = tid >> 1;
    const int a_kq  = (tid & 1) << 2;
    const int b_k   = tid >> 5;
    const int b_n   = (tid & 31) << 2;

    int m  = m0 + a_row;
    int mm = (m < cnt) ? m : (cnt - 1);
    const float* __restrict__ Arow =
        (ASRC == 0) ? Abase + (size_t)g_pair_token[off + mm] * KDIM
                    : Abase + (size_t)(off + mm) * KDIM;

    const int tx = tid & 15;
    const int ty = tid >> 4;

    unsigned long long acc2[8][4];
    #pragma unroll
    for (int i = 0; i < 8; i++)
        #pragma unroll
        for (int p = 0; p < 4; p++) acc2[i][p] = 0ULL;

    // prologue: tile 0
    {
        float4 av = *reinterpret_cast<const float4*>(Arow + a_kq);
        float4 bv = *reinterpret_cast<const float4*>(Wb + (size_t)b_k * NDIM + n0 + b_n);
        As[0][a_kq + 0][a_row] = av.x;
        As[0][a_kq + 1][a_row] = av.y;
        As[0][a_kq + 2][a_row] = av.z;
        As[0][a_kq + 3][a_row] = av.w;
        *reinterpret_cast<float4*>(&Bs[0][b_k][b_n]) = bv;
    }
    __syncthreads();

    const int ntiles = KDIM / BK;
    for (int t = 0; t < ntiles; ++t) {
        const int cur = t & 1;
        const int nxt = cur ^ 1;
        float4 an, bn;
        if (t + 1 < ntiles) {
            const int k0 = (t + 1) * BK;
            an = *reinterpret_cast<const float4*>(Arow + k0 + a_kq);
            bn = *reinterpret_cast<const float4*>(Wb + (size_t)(k0 + b_k) * NDIM + n0 + b_n);
        }
        #pragma unroll
        for (int kk = 0; kk < BK; kk++) {
            float ar[8];
            *reinterpret_cast<float4*>(&ar[0]) = *reinterpret_cast<const float4*>(&As[cur][kk][ty * 8]);
            *reinterpret_cast<float4*>(&ar[4]) = *reinterpret_cast<const float4*>(&As[cur][kk][ty * 8 + 4]);
            unsigned long long brp[4];
            #pragma unroll
            for (int p = 0; p < 4; p++)
                brp[p] = packf2(Bs[cur][kk][tx + 32 * p], Bs[cur][kk][tx + 32 * p + 16]);
            #pragma unroll
            for (int i = 0; i < 8; i++) {
                unsigned long long arr = packf2(ar[i], ar[i]);
                #pragma unroll
                for (int p = 0; p < 4; p++)
                    FMA2(acc2[i][p], arr, brp[p]);
            }
        }
        if (t + 1 < ntiles) {
            As[nxt][a_kq + 0][a_row] = an.x;
            As[nxt][a_kq + 1][a_row] = an.y;
            As[nxt][a_kq + 2][a_row] = an.z;
            As[nxt][a_kq + 3][a_row] = an.w;
            *reinterpret_cast<float4*>(&Bs[nxt][b_k][b_n]) = bn;
        }
        __syncthreads();
    }

    // epilogue: cols n0 + tx + 32p (+16)
    float bias0[4], bias1[4];
    #pragma unroll
    for (int p = 0; p < 4; p++) {
        bias0[p] = bstack[(size_t)e * NDIM + n0 + tx + 32 * p];
        bias1[p] = bstack[(size_t)e * NDIM + n0 + tx + 32 * p + 16];
    }
    #pragma unroll
    for (int i = 0; i < 8; i++) {
        int mr = m0 + ty * 8 + i;
        if (mr >= cnt) continue;
        float* orow = Obase + (size_t)(off + mr) * NDIM + n0 + tx;
        #pragma unroll
        for (int p = 0; p < 4; p++) {
            float lo, hi;
            unpackf2(acc2[i][p], lo, hi);
            float v0 = lo + bias0[p];
            float v1 = hi + bias1[p];
            if (EPI == 0) { v0 = fmaxf(v0, 0.f); v1 = fmaxf(v1, 0.f); }
            orow[32 * p]      = v0;
            orow[32 * p + 16] = v1;
        }
    }
}

// ==================== combine + finalize ====================
__global__ __launch_bounds__(256)
void combine_kernel(float* __restrict__ out)
{
    int i = blockIdx.x * 256 + threadIdx.x;
    int tok = i >> 10, c = i & 1023;
    float v = g_tok_s[tok * 2 + 0] * g_o_pair[(size_t)g_tok_pos[tok * 2 + 0] * D_OUT_ + c]
            + g_tok_s[tok * 2 + 1] * g_o_pair[(size_t)g_tok_pos[tok * 2 + 1] * D_OUT_ + c];
    out[i] = v;
}

__global__ __launch_bounds__(1024)
void finalize_kernel(float* __restrict__ out, long long out_sz)
{
    __shared__ float red[1024];
    const int tid = threadIdx.x;
    float s = 0.f;
    for (int i = tid; i < B_; i += 1024) s += g_entropy[i];
    red[tid] = s;
    __syncthreads();
    for (int st = 512; st > 0; st >>= 1) {
        if (tid < st) red[tid] += red[tid + st];
        __syncthreads();
    }
    if (tid == 0) {
        float ent_mean = red[0] / (float)B_;
        float load[E_];
        float mean = 0.f;
        for (int e = 0; e < E_; e++) {
            load[e] = (float)g_counts[e] / ((float)B_ + 1e-9f);
            mean += load[e];
        }
        mean /= (float)E_;
        float var = 0.f;
        for (int e = 0; e < E_; e++) {
            float d = load[e] - mean;
            var += d * d;
        }
        var /= (float)(E_ - 1);
        float aux = 5.0f * var + 0.1f * ent_mean;
        long long aux_off = (long long)B_ * D_OUT_;
        if (out_sz > aux_off) out[aux_off] = aux;
    }
}

// ==================== launch ====================
extern "C" void kernel_launch(void* const* d_in, const int* in_sizes, int n_in,
                              void* d_out, int out_size)
{
    const float* x   = (const float*)d_in[0];
    const float* We1 = (const float*)d_in[1];
    const float* be1 = (const float*)d_in[2];
    const float* We2 = (const float*)d_in[3];
    const float* be2 = (const float*)d_in[4];
    const float* We3 = (const float*)d_in[5];
    const float* be3 = (const float*)d_in[6];
    const float* Wg1 = (const float*)d_in[7];
    const float* bg1 = (const float*)d_in[8];
    const float* Wg2 = (const float*)d_in[9];
    const float* bg2 = (const float*)d_in[10];
    const float* Wg3 = (const float*)d_in[11];
    const float* bg3 = (const float*)d_in[12];
    float* out = (float*)d_out;
    long long out_sz = (long long)out_size;

    init_kernel<<<1, 32>>>();
    gate_kernel<<<B_ / 8, 128>>>(x, Wg1, bg1, Wg2, bg2, Wg3, bg3, out, out_sz);
    offsets_kernel<<<1, 32>>>();
    scatter_kernel<<<(B_ + 255) / 256, 256>>>();

    const int max_mt = B_ / 128;   // per-expert cnt <= B
    dim3 g1(D_HID_ / BN, max_mt, E_);
    dim3 g3(D_OUT_ / BN, max_mt, E_);

    moe_gemm2<D_IN_,  D_HID_, 0, 0><<<g1, 256>>>(x, We1, be1);
    moe_gemm2<D_HID_, D_HID_, 0, 1><<<g1, 256>>>(x, We2, be2);
    moe_gemm2<D_HID_, D_OUT_, 2, 2><<<g3, 256>>>(x, We3, be3);

    combine_kernel<<<(B_ * D_OUT_) / 256, 256>>>(out);
    finalize_kernel<<<1, 1024>>>(out, out_sz);
}